// round 5
// baseline (speedup 1.0000x reference)
#include <cuda_runtime.h>
#include <cuda_fp16.h>

// out[v,:] = coef * ( 2*x[v,:]*S1 + S2 ), S1 = sum_k x[nbr[v,k]], S2 = sum_k x[nbr[v,k]]^2
// N=100000, K=16, D=128, coef = (2/6)/16 = 1/48.
// L2 bandwidth is the binding resource (pinned ~75% across all fp32 variants).
// Halve the dominant gather traffic: pre-convert x to fp16 in a __device__
// scratch (25.6 MB; x + xh together fit in the 126 MB L2), gather 256B rows
// (one LDG.64 per lane), accumulate in fp32. Self row stays exact fp32.

#define TMP_N 100000
#define TMP_D 128
#define TMP_K 16

// fp16 copy of x: [N, D] halves = [N, 32] uint2 (4 halves per lane).
__device__ __align__(16) uint2 g_xh[TMP_N * TMP_D / 4];

__global__ __launch_bounds__(256) void TMP_convert_kernel(
    const float4* __restrict__ x, int n4)
{
    int i = blockIdx.x * blockDim.x + threadIdx.x;
    if (i >= n4) return;
    float4 v = __ldg(&x[i]);
    __half2 h0 = __floats2half2_rn(v.x, v.y);
    __half2 h1 = __floats2half2_rn(v.z, v.w);
    uint2 p;
    p.x = *reinterpret_cast<unsigned int*>(&h0);
    p.y = *reinterpret_cast<unsigned int*>(&h1);
    g_xh[i] = p;
}

__global__ __launch_bounds__(256) void TMessagePassing_11974368821731_kernel(
    const float4* __restrict__ x,      // [N, 32] float4 (exact self rows)
    const int*    __restrict__ nbr,    // [N, 16]
    float4*       __restrict__ out,    // [N, 32] float4
    int n)
{
    int warp = (int)((blockIdx.x * blockDim.x + threadIdx.x) >> 5);
    int lane = threadIdx.x & 31;
    if (warp >= n) return;

    const float coef  = 1.0f / 48.0f;
    const float coef2 = 2.0f / 48.0f;

    // Preload all 16 neighbor indices (uniform across warp -> broadcast).
    const int* nv = nbr + warp * TMP_K;
    int idx[TMP_K];
#pragma unroll
    for (int k = 0; k < TMP_K; k++) idx[k] = __ldg(&nv[k]);

    // Exact fp32 self row (independent of gathers, issued early).
    float4 xv = __ldg(&x[(long long)warp * 32 + lane]);

    float4 s1 = make_float4(0.f, 0.f, 0.f, 0.f);
    float4 s2 = make_float4(0.f, 0.f, 0.f, 0.f);

    // 16 independent LDG.64 gathers of fp16 rows (256B/row), fp32 accumulation.
#pragma unroll
    for (int k = 0; k < TMP_K; k++) {
        uint2 p = __ldg(&g_xh[(long long)idx[k] * 32 + lane]);
        __half2 h0 = *reinterpret_cast<__half2*>(&p.x);
        __half2 h1 = *reinterpret_cast<__half2*>(&p.y);
        float2 u0 = __half22float2(h0);
        float2 u1 = __half22float2(h1);
        s1.x += u0.x; s1.y += u0.y; s1.z += u1.x; s1.w += u1.y;
        s2.x = fmaf(u0.x, u0.x, s2.x);
        s2.y = fmaf(u0.y, u0.y, s2.y);
        s2.z = fmaf(u1.x, u1.x, s2.z);
        s2.w = fmaf(u1.y, u1.y, s2.w);
    }

    float4 o;
    o.x = fmaf(coef2 * xv.x, s1.x, coef * s2.x);
    o.y = fmaf(coef2 * xv.y, s1.y, coef * s2.y);
    o.z = fmaf(coef2 * xv.z, s1.z, coef * s2.z);
    o.w = fmaf(coef2 * xv.w, s1.w, coef * s2.w);

    // Streaming store: keep out from evicting x/xh in L2.
    __stcs(&out[(long long)warp * 32 + lane], o);
}

extern "C" void kernel_launch(void* const* d_in, const int* in_sizes, int n_in,
                              void* d_out, int out_size)
{
    const float4* x   = (const float4*)d_in[0];
    const int*    nbr = (const int*)d_in[1];
    float4*       out = (float4*)d_out;

    int n  = in_sizes[1] / TMP_K;      // N nodes
    int n4 = in_sizes[0] / 4;          // N*D/4 float4s

    TMP_convert_kernel<<<(n4 + 255) / 256, 256>>>(x, n4);

    int warps_per_block = 256 / 32;    // 8 nodes per block
    int blocks = (n + warps_per_block - 1) / warps_per_block;
    TMessagePassing_11974368821731_kernel<<<blocks, 256>>>(x, nbr, out, n);
}

// round 6
// speedup vs baseline: 1.0078x; 1.0078x over previous
#include <cuda_runtime.h>
#include <cuda_fp16.h>

// out[v,:] = coef * ( 2*x[v,:]*S1 + S2 ), S1 = sum_k x[nbr[v,k]], S2 = sum_k x[nbr[v,k]]^2
// N=100000, K=16, D=128, coef = (2/6)/16 = 1/48.
// fp16 route. Main kernel is ISSUE-bound (70%), so: accumulate gathers in
// half2 (HADD2/HFMA2) in runs of 4 and flush to fp32 (cuts ~26% of instrs),
// and read the self row from the fp16 scratch too (drops the 51MB fp32 x
// stream from the main kernel). Accuracy budget ~3-4e-4 vs 1e-3 threshold.

#define TMP_N 100000
#define TMP_D 128
#define TMP_K 16

// fp16 copy of x: [N, D] halves = [N, 32] uint2 (4 halves per lane).
__device__ __align__(16) uint2 g_xh[TMP_N * TMP_D / 4];

__global__ __launch_bounds__(256) void TMP_convert_kernel(
    const float4* __restrict__ x, int n4)
{
    int i = blockIdx.x * blockDim.x + threadIdx.x;
    if (i >= n4) return;
    float4 v = __ldg(&x[i]);
    __half2 h0 = __floats2half2_rn(v.x, v.y);
    __half2 h1 = __floats2half2_rn(v.z, v.w);
    uint2 p;
    p.x = *reinterpret_cast<unsigned int*>(&h0);
    p.y = *reinterpret_cast<unsigned int*>(&h1);
    g_xh[i] = p;
}

static __device__ __forceinline__ __half2 h2bits(unsigned int u) {
    return *reinterpret_cast<__half2*>(&u);
}

__global__ __launch_bounds__(256) void TMessagePassing_11974368821731_kernel(
    const int*  __restrict__ nbr,    // [N, 16]
    float4*     __restrict__ out,    // [N, 32] float4
    int n)
{
    int warp = (int)((blockIdx.x * blockDim.x + threadIdx.x) >> 5);
    int lane = threadIdx.x & 31;
    if (warp >= n) return;

    const float coef  = 1.0f / 48.0f;
    const float coef2 = 2.0f / 48.0f;

    const uint2* __restrict__ xh = g_xh;

    // Preload all 16 neighbor indices (uniform across warp -> broadcast).
    const int* nv = nbr + warp * TMP_K;
    int idx[TMP_K];
#pragma unroll
    for (int k = 0; k < TMP_K; k++) idx[k] = __ldg(&nv[k]);

    // Self row from fp16 scratch (L2-resident), issued early.
    uint2 ps = __ldg(&xh[(long long)warp * 32 + lane]);

    float4 s1 = make_float4(0.f, 0.f, 0.f, 0.f);
    float4 s2 = make_float4(0.f, 0.f, 0.f, 0.f);

    // 4 blocks of 4 gathers; accumulate each block in half2, flush to fp32.
#pragma unroll
    for (int b = 0; b < 4; b++) {
        __half2 t0, t1, q0, q1;
        {
            uint2 p = __ldg(&xh[(long long)idx[4 * b] * 32 + lane]);
            __half2 a0 = h2bits(p.x), a1 = h2bits(p.y);
            t0 = a0;               t1 = a1;
            q0 = __hmul2(a0, a0);  q1 = __hmul2(a1, a1);
        }
#pragma unroll
        for (int j = 1; j < 4; j++) {
            uint2 p = __ldg(&xh[(long long)idx[4 * b + j] * 32 + lane]);
            __half2 a0 = h2bits(p.x), a1 = h2bits(p.y);
            t0 = __hadd2(t0, a0);      t1 = __hadd2(t1, a1);
            q0 = __hfma2(a0, a0, q0);  q1 = __hfma2(a1, a1, q1);
        }
        float2 f;
        f = __half22float2(t0); s1.x += f.x; s1.y += f.y;
        f = __half22float2(t1); s1.z += f.x; s1.w += f.y;
        f = __half22float2(q0); s2.x += f.x; s2.y += f.y;
        f = __half22float2(q1); s2.z += f.x; s2.w += f.y;
    }

    float2 xv0 = __half22float2(h2bits(ps.x));
    float2 xv1 = __half22float2(h2bits(ps.y));

    float4 o;
    o.x = fmaf(coef2 * xv0.x, s1.x, coef * s2.x);
    o.y = fmaf(coef2 * xv0.y, s1.y, coef * s2.y);
    o.z = fmaf(coef2 * xv1.x, s1.z, coef * s2.z);
    o.w = fmaf(coef2 * xv1.y, s1.w, coef * s2.w);

    // Streaming store: keep out from evicting xh in L2.
    __stcs(&out[(long long)warp * 32 + lane], o);
}

extern "C" void kernel_launch(void* const* d_in, const int* in_sizes, int n_in,
                              void* d_out, int out_size)
{
    const float4* x   = (const float4*)d_in[0];
    const int*    nbr = (const int*)d_in[1];
    float4*       out = (float4*)d_out;

    int n  = in_sizes[1] / TMP_K;      // N nodes
    int n4 = in_sizes[0] / 4;          // N*D/4 float4s

    TMP_convert_kernel<<<(n4 + 255) / 256, 256>>>(x, n4);

    int warps_per_block = 256 / 32;    // 8 nodes per block
    int blocks = (n + warps_per_block - 1) / warps_per_block;
    TMessagePassing_11974368821731_kernel<<<blocks, 256>>>(nbr, out, n);
}